// round 4
// baseline (speedup 1.0000x reference)
#include <cuda_runtime.h>
#include <math.h>

#define B_    8
#define T_    2048
#define DIMC  512
#define NH_   8
#define NKV_  4
#define HD_   64
#define KVD_  256

// Scratch (no dynamic allocation allowed)
__device__ float g_q[B_ * T_ * DIMC];
__device__ float g_k[B_ * T_ * KVD_];
__device__ float g_v[B_ * T_ * KVD_];
__device__ float g_y[B_ * T_ * DIMC];

// ---------------------------------------------------------------------------
// Packed f32x2 helpers (sm_103a FFMA2 — ptxas never emits these from C++)
// ---------------------------------------------------------------------------
typedef unsigned long long u64t;

__device__ __forceinline__ u64t f2pack(float lo, float hi) {
    u64t r; asm("mov.b64 %0, {%1, %2};" : "=l"(r) : "f"(lo), "f"(hi)); return r;
}
__device__ __forceinline__ u64t fbcast(float x) {
    u64t r; asm("mov.b64 %0, {%1, %1};" : "=l"(r) : "f"(x)); return r;
}
__device__ __forceinline__ void f2unpack(u64t v, float& lo, float& hi) {
    asm("mov.b64 {%0, %1}, %2;" : "=f"(lo), "=f"(hi) : "l"(v));
}
__device__ __forceinline__ u64t ffma2(u64t a, u64t b, u64t c) {
    u64t d; asm("fma.rn.f32x2 %0, %1, %2, %3;" : "=l"(d) : "l"(a), "l"(b), "l"(c));
    return d;
}
__device__ __forceinline__ u64t fmul2(u64t a, u64t b) {
    u64t d; asm("mul.rn.f32x2 %0, %1, %2;" : "=l"(d) : "l"(a), "l"(b));
    return d;
}
// 16B shared load straight into two 64-bit regs (no pack MOVs)
__device__ __forceinline__ void lds_v2u64(const void* p, u64t& a, u64t& b) {
    unsigned s = (unsigned)__cvta_generic_to_shared(p);
    asm volatile("ld.shared.v2.b64 {%0, %1}, [%2];" : "=l"(a), "=l"(b) : "r"(s));
}

// ---------------------------------------------------------------------------
// GEMM: C[M,N] = A[M,K] @ W[N,K]^T   (both row-major). 64x64 tile, BK=16,
// 256 threads, 4x4 register blocking (acc held as 4x2 packed f32x2).
// ---------------------------------------------------------------------------
__global__ __launch_bounds__(256) void gemm_tn(const float* __restrict__ A,
                                               const float* __restrict__ W,
                                               float* __restrict__ C,
                                               int N, int K) {
    __shared__ float As[16][64];
    __shared__ float Ws[16][64];
    int tid = threadIdx.x;
    int m0 = blockIdx.y * 64, n0 = blockIdx.x * 64;
    int tx = tid & 15, ty = tid >> 4;
    int lrow = tid >> 2, lk = (tid & 3) * 4;

    u64t acc[4][2];
#pragma unroll
    for (int i = 0; i < 4; i++) { acc[i][0] = 0ULL; acc[i][1] = 0ULL; }

    const float* Ap  = A + (size_t)(m0 + lrow) * K + lk;
    const float* Wp_ = W + (size_t)(n0 + lrow) * K + lk;

    for (int k0 = 0; k0 < K; k0 += 16) {
        float4 av = *(const float4*)(Ap + k0);
        float4 wv = *(const float4*)(Wp_ + k0);
        As[lk + 0][lrow] = av.x; As[lk + 1][lrow] = av.y;
        As[lk + 2][lrow] = av.z; As[lk + 3][lrow] = av.w;
        Ws[lk + 0][lrow] = wv.x; Ws[lk + 1][lrow] = wv.y;
        Ws[lk + 2][lrow] = wv.z; Ws[lk + 3][lrow] = wv.w;
        __syncthreads();
#pragma unroll
        for (int k = 0; k < 16; k++) {
            float4 a = *(const float4*)&As[k][ty * 4];
            u64t wn01, wn23;
            lds_v2u64(&Ws[k][tx * 4], wn01, wn23);
            float am[4] = {a.x, a.y, a.z, a.w};
#pragma unroll
            for (int i = 0; i < 4; i++) {
                u64t am2 = fbcast(am[i]);
                acc[i][0] = ffma2(am2, wn01, acc[i][0]);
                acc[i][1] = ffma2(am2, wn23, acc[i][1]);
            }
        }
        __syncthreads();
    }
#pragma unroll
    for (int i = 0; i < 4; i++) {
        float4 r;
        f2unpack(acc[i][0], r.x, r.y);
        f2unpack(acc[i][1], r.z, r.w);
        *(float4*)(C + (size_t)(m0 + ty * 4 + i) * N + n0 + tx * 4) = r;
    }
}

// ---------------------------------------------------------------------------
// Fused per-head RMS norm + RoPE. One warp per head; lane l owns the rotation
// pair (l, l+32). grid = B*T rows, block = nh*32.
// ---------------------------------------------------------------------------
__global__ void normrope(float* __restrict__ buf, int nh) {
    int row  = blockIdx.x;            // b*T + t
    int t    = row & (T_ - 1);
    int h    = threadIdx.x >> 5;
    int lane = threadIdx.x & 31;
    float* p = buf + (size_t)row * (nh * HD_) + h * HD_;

    float x1 = p[lane];
    float x2 = p[lane + 32];
    float ss = x1 * x1 + x2 * x2;
#pragma unroll
    for (int o = 16; o; o >>= 1) ss += __shfl_xor_sync(0xffffffffu, ss, o);
    float r = rsqrtf(ss * (1.0f / 64.0f) + 1.1920928955078125e-07f);

    float inv = powf(10000.0f, -(float)(2 * lane) / 64.0f);
    float f   = (float)t * inv;
    float s   = sinf(f);
    float c   = cosf(f);

    x1 *= r; x2 *= r;
    p[lane]      = x1 * c + x2 * s;
    p[lane + 32] = -x1 * s + x2 * c;
}

// ---------------------------------------------------------------------------
// Causal flash attention, fp32 with packed f32x2 math. One thread per query
// row (BM=128 rows/block), K/V tiles (BN=32 x 64) in SMEM, online softmax.
// ---------------------------------------------------------------------------
#define BM 128
#define BN 32

__global__ __launch_bounds__(128) void attn(const float* __restrict__ Q,
                                            const float* __restrict__ Kg,
                                            const float* __restrict__ Vg,
                                            float* __restrict__ Y) {
    __shared__ float Ks[BN][HD_];
    __shared__ float Vs[BN][HD_];

    int tid = threadIdx.x;
    int qb = blockIdx.x, h = blockIdx.y, b = blockIdx.z;
    int m  = qb * BM + tid;           // this thread's query row
    int hk = h >> 1;                  // GQA: rep = NH/NKV = 2

    const float* qp = Q + (size_t)(b * T_ + m) * DIMC + h * HD_;
    u64t q2[HD_ / 2];                 // q pre-scaled, packed in pairs
#pragma unroll
    for (int d = 0; d < HD_; d += 4) {
        float4 v4 = *(const float4*)(qp + d);
        q2[d / 2 + 0] = f2pack(v4.x * 0.125f, v4.y * 0.125f);
        q2[d / 2 + 1] = f2pack(v4.z * 0.125f, v4.w * 0.125f);
    }
    u64t o2[HD_ / 2];
#pragma unroll
    for (int d = 0; d < HD_ / 2; d++) o2[d] = 0ULL;
    float mi = -INFINITY, l = 0.f;

    int kend = qb * BM + BM;          // exclusive causal bound for this block
    for (int k0 = 0; k0 < kend; k0 += BN) {
        // cooperative tile load (float4, coalesced)
#pragma unroll
        for (int i = 0; i < 4; i++) {
            int e  = tid + 128 * i;           // 0..511 float4 slots
            int j  = e >> 4;
            int d4 = (e & 15) << 2;
            size_t gb = (size_t)(b * T_ + k0 + j) * KVD_ + hk * HD_ + d4;
            *(float4*)&Ks[j][d4] = *(const float4*)(Kg + gb);
            *(float4*)&Vs[j][d4] = *(const float4*)(Vg + gb);
        }
        __syncthreads();

        float s[BN];
#pragma unroll
        for (int j = 0; j < BN; j++) {
            u64t acca = 0ULL, accb = 0ULL;
#pragma unroll
            for (int d = 0; d < HD_; d += 4) {
                u64t k01, k23;
                lds_v2u64(&Ks[j][d], k01, k23);
                acca = ffma2(q2[d / 2 + 0], k01, acca);
                accb = ffma2(q2[d / 2 + 1], k23, accb);
            }
            float alo, ahi, blo, bhi;
            f2unpack(acca, alo, ahi);
            f2unpack(accb, blo, bhi);
            float acc = (alo + ahi) + (blo + bhi);
            s[j] = (k0 + j <= m) ? acc : -INFINITY;
        }

        float tmax = -INFINITY;
#pragma unroll
        for (int j = 0; j < BN; j++) tmax = fmaxf(tmax, s[j]);
        float mnew = fmaxf(mi, tmax);
        float corr = __expf(mi - mnew);       // 0 on first live tile
        float psum = 0.f;
#pragma unroll
        for (int j = 0; j < BN; j++) {
            float pj = __expf(s[j] - mnew);   // exp(-inf)=0 handles mask
            s[j] = pj;
            psum += pj;
        }
        l = l * corr + psum;
        u64t corr2 = fbcast(corr);
#pragma unroll
        for (int d = 0; d < HD_ / 2; d++) o2[d] = fmul2(corr2, o2[d]);
#pragma unroll
        for (int j = 0; j < BN; j++) {
            u64t pj2 = fbcast(s[j]);
#pragma unroll
            for (int d = 0; d < HD_; d += 4) {
                u64t v01, v23;
                lds_v2u64(&Vs[j][d], v01, v23);
                o2[d / 2 + 0] = ffma2(pj2, v01, o2[d / 2 + 0]);
                o2[d / 2 + 1] = ffma2(pj2, v23, o2[d / 2 + 1]);
            }
        }
        mi = mnew;
        __syncthreads();
    }

    float invl = 1.f / l;
    float* yp = Y + (size_t)(b * T_ + m) * DIMC + h * HD_;   // [B,T,H*D] direct
#pragma unroll
    for (int d = 0; d < HD_; d += 4) {
        float4 r;
        f2unpack(o2[d / 2 + 0], r.x, r.y);
        f2unpack(o2[d / 2 + 1], r.z, r.w);
        r.x *= invl; r.y *= invl; r.z *= invl; r.w *= invl;
        *(float4*)(yp + d) = r;
    }
}

// ---------------------------------------------------------------------------
extern "C" void kernel_launch(void* const* d_in, const int* in_sizes, int n_in,
                              void* d_out, int out_size) {
    const float* x  = (const float*)d_in[0];
    const float* Wq = (const float*)d_in[1];
    const float* Wk = (const float*)d_in[2];
    const float* Wv = (const float*)d_in[3];
    const float* Wp = (const float*)d_in[4];
    float* out = (float*)d_out;

    float *q, *k, *v, *y;
    cudaGetSymbolAddress((void**)&q, g_q);
    cudaGetSymbolAddress((void**)&k, g_k);
    cudaGetSymbolAddress((void**)&v, g_v);
    cudaGetSymbolAddress((void**)&y, g_y);

    const int M = B_ * T_;                       // 16384
    dim3 gq(DIMC / 64, M / 64);                  // 8 x 256
    dim3 gkv(KVD_ / 64, M / 64);                 // 4 x 256

    gemm_tn<<<gq,  256>>>(x, Wq, q, DIMC, DIMC);
    gemm_tn<<<gkv, 256>>>(x, Wk, k, KVD_, DIMC);
    gemm_tn<<<gkv, 256>>>(x, Wv, v, KVD_, DIMC);

    normrope<<<M, NH_  * 32>>>(q, NH_);
    normrope<<<M, NKV_ * 32>>>(k, NKV_);

    attn<<<dim3(T_ / BM, NH_, B_), BM>>>(q, k, v, y);

    gemm_tn<<<gq, 256>>>(y, Wp, out, DIMC, DIMC);
}